// round 16
// baseline (speedup 1.0000x reference)
#include <cuda_runtime.h>
#include <cstdint>

#define NN 50000
#define NE 800000
#define DIM 128
#define KC 5000

// ---------------- scratch (static device globals; no allocation) -------------
__device__ float g_h1[NN * DIM];     // dinv ⊙ (x@W1); reused as edge scratch after conv1
__device__ float g_x1[NN * DIM];
__device__ float g_gate[NN];
__device__ float g_dinv[NN];
__device__ unsigned g_ukey[NN];
__device__ int g_keep[NN];
__device__ int g_cid[NN];
__device__ int g_degin[NN];
__device__ int g_deg2[NN];
__device__ int g_off1[NN + 1];
__device__ int g_cur1[NN];
__device__ int g_csr1[NE];
__device__ unsigned long long g_bestkey[NN];
__device__ unsigned long long g_knode[NN];
__device__ float g_sums[KC * DIM];
__device__ float g_cntf[KC];
__device__ float g_h2[KC * DIM];     // (dinvc/cnt) ⊙ (sums@W2)
__device__ float g_xp2[KC * DIM];
__device__ int g_degc[KC];
__device__ int g_off2[KC + 1];
__device__ int g_cur2[KC];
__device__ int g_csr2[NE];
__device__ int g_bsum[64];
__device__ unsigned g_h16[65536];
__device__ unsigned g_hlo[65536];
__device__ unsigned g_p16;
__device__ unsigned g_thr;
__device__ int g_need;
__device__ int g_cnteq;
__device__ unsigned long long g_fbkey;
__device__ int g_kctr;
__device__ int g_maxdeg;

// ---------------- init / zero ------------------------------------------------
__global__ void k_zero() {
    int i = blockIdx.x * blockDim.x + threadIdx.x;
    if (i < NN) { g_degin[i] = 0; g_deg2[i] = 0; g_cur1[i] = 0; g_bestkey[i] = 0ULL; }
    if (i < KC) { g_cntf[i] = 0.f; g_degc[i] = 0; g_cur2[i] = 0; }
    if (i < KC * DIM) g_sums[i] = 0.f;
    if (i < 65536) { g_h16[i] = 0u; g_hlo[i] = 0u; }
    if (i == 0) { g_fbkey = 0ULL; g_kctr = 0; g_maxdeg = 0; }
}

// ---------------- degrees ----------------------------------------------------
__global__ void k_deg(const int* __restrict__ row, const int* __restrict__ col) {
    int e = blockIdx.x * blockDim.x + threadIdx.x;
    if (e >= NE) return;
    atomicAdd(&g_degin[col[e]], 1);
    atomicAdd(&g_deg2[row[e]], 1);
}

// ---------------- multi-block 3-phase exclusive scan (+optional dinv) ----------
__global__ void k_scanp(const int* __restrict__ in, int* __restrict__ out,
                        int* __restrict__ bsum, int n, float* __restrict__ dinv) {
    __shared__ int wsum[32];
    int tid = threadIdx.x, lane = tid & 31, w = tid >> 5;
    int gid = blockIdx.x * 1024 + tid;
    int v = (gid < n) ? in[gid] : 0;
    if (dinv && gid < n) dinv[gid] = rsqrtf((float)v + 1.f);
    int sc = v;
#pragma unroll
    for (int o = 1; o < 32; o <<= 1) {
        int t2 = __shfl_up_sync(0xffffffffu, sc, o);
        if (lane >= o) sc += t2;
    }
    if (lane == 31) wsum[w] = sc;
    __syncthreads();
    if (w == 0) {
        int ws = wsum[lane];
#pragma unroll
        for (int o = 1; o < 32; o <<= 1) {
            int t2 = __shfl_up_sync(0xffffffffu, ws, o);
            if (lane >= o) ws += t2;
        }
        wsum[lane] = ws;
    }
    __syncthreads();
    int excl = (w ? wsum[w - 1] : 0) + sc - v;
    if (gid < n) out[gid] = excl;
    if (tid == 0) bsum[blockIdx.x] = wsum[31];
}

// single-warp scan of up to 64 block sums (replaces 1-thread serial loop)
__global__ void k_scanb(int* __restrict__ bsum, int nb, int* __restrict__ out, int n) {
    int lane = threadIdx.x;   // 32 threads
    int v0 = (lane < nb) ? bsum[lane] : 0;
    int v1 = (lane + 32 < nb) ? bsum[lane + 32] : 0;
    int s0 = v0;
#pragma unroll
    for (int o = 1; o < 32; o <<= 1) {
        int t = __shfl_up_sync(0xffffffffu, s0, o);
        if (lane >= o) s0 += t;
    }
    int tot0 = __shfl_sync(0xffffffffu, s0, 31);
    int s1 = v1;
#pragma unroll
    for (int o = 1; o < 32; o <<= 1) {
        int t = __shfl_up_sync(0xffffffffu, s1, o);
        if (lane >= o) s1 += t;
    }
    s1 += tot0;
    if (lane < nb) bsum[lane] = s0 - v0;
    if (lane + 32 < nb) bsum[lane + 32] = s1 - v1;
    if (lane == 31) out[n] = s1;   // grand total (v1 zero-padded)
}

__global__ void k_scana(int* __restrict__ out, const int* __restrict__ bsum, int n) {
    int gid = blockIdx.x * 1024 + threadIdx.x;
    if (gid < n) out[gid] += bsum[blockIdx.x];
}

// ---------------- CSR scatter (group edges by col) ----------------------------
__global__ void k_scat1(const int* __restrict__ row, const int* __restrict__ col) {
    int e = blockIdx.x * blockDim.x + threadIdx.x;
    if (e >= NE) return;
    int c = col[e];
    int p = g_off1[c] + atomicAdd(&g_cur1[c], 1);
    g_csr1[p] = row[e];
}

// ---------------- fp32 SMEM GEMM: 128x128 tile, 8x8 per-thread ----------------
__global__ void __launch_bounds__(256) k_gemm(
    const float* __restrict__ A, const float* __restrict__ W,
    float* __restrict__ C, int M,
    const int* __restrict__ degA,
    const float* __restrict__ cntA,
    const float* __restrict__ bias,
    const float* __restrict__ bcast, const int* __restrict__ cid)
{
    __shared__ float As[16][132];   // transposed: As[k][row], 128 rows
    __shared__ float Ws[16][128];
    int tid = threadIdx.x;
    int tx = tid & 15, ty = tid >> 4;       // 16 x 16 thread map
    int row0 = blockIdx.x * 128;
    float acc[8][8];
#pragma unroll
    for (int i = 0; i < 8; i++)
#pragma unroll
        for (int j = 0; j < 8; j++) acc[i][j] = 0.f;

    for (int kt = 0; kt < 128; kt += 16) {
#pragma unroll
        for (int it = 0; it < 2; it++) {     // A: 128 rows x 16 k -> 512 float4
            int idx = tid + it * 256;        // 0..511
            int r = idx >> 2;                // 0..127
            int k4 = (idx & 3) * 4;
            int gr = row0 + r;
            float4 a = (gr < M) ? *(const float4*)&A[(size_t)gr * 128 + kt + k4]
                                : make_float4(0.f, 0.f, 0.f, 0.f);
            As[k4 + 0][r] = a.x; As[k4 + 1][r] = a.y;
            As[k4 + 2][r] = a.z; As[k4 + 3][r] = a.w;
        }
#pragma unroll
        for (int it = 0; it < 2; it++) {     // W: 16 k x 128 n
            int idx = tid + it * 256;
            int kk = idx >> 5, n4 = idx & 31;
            *(float4*)&Ws[kk][n4 * 4] = *(const float4*)&W[(size_t)(kt + kk) * 128 + n4 * 4];
        }
        __syncthreads();
#pragma unroll
        for (int kk = 0; kk < 16; kk++) {
            float4 a0 = *(const float4*)&As[kk][ty * 8];
            float4 a1 = *(const float4*)&As[kk][ty * 8 + 4];
            float4 w0 = *(const float4*)&Ws[kk][tx * 8];
            float4 w1 = *(const float4*)&Ws[kk][tx * 8 + 4];
            float a_[8] = {a0.x, a0.y, a0.z, a0.w, a1.x, a1.y, a1.z, a1.w};
            float w_[8] = {w0.x, w0.y, w0.z, w0.w, w1.x, w1.y, w1.z, w1.w};
#pragma unroll
            for (int i = 0; i < 8; i++)
#pragma unroll
                for (int j = 0; j < 8; j++) acc[i][j] += a_[i] * w_[j];
        }
        __syncthreads();
    }
#pragma unroll
    for (int i = 0; i < 8; i++) {
        int r = row0 + ty * 8 + i;
        if (r >= M) continue;
        float rs = 1.f;
        if (degA) rs = rsqrtf((float)degA[r] + 1.f);
        if (cntA) rs /= fmaxf(cntA[r], 1.f);
        float4 o0 = make_float4(acc[i][0], acc[i][1], acc[i][2], acc[i][3]);
        float4 o1 = make_float4(acc[i][4], acc[i][5], acc[i][6], acc[i][7]);
        o0.x *= rs; o0.y *= rs; o0.z *= rs; o0.w *= rs;
        o1.x *= rs; o1.y *= rs; o1.z *= rs; o1.w *= rs;
        if (bias) {
            float4 b0 = *(const float4*)&bias[tx * 8];
            float4 b1v = *(const float4*)&bias[tx * 8 + 4];
            o0.x += b0.x; o0.y += b0.y; o0.z += b0.z; o0.w += b0.w;
            o1.x += b1v.x; o1.y += b1v.y; o1.z += b1v.z; o1.w += b1v.w;
        }
        if (bcast) {
            const float* bc = &bcast[(size_t)cid[r] * 128];
            float4 c0 = *(const float4*)&bc[tx * 8];
            float4 c1 = *(const float4*)&bc[tx * 8 + 4];
            o0.x += c0.x; o0.y += c0.y; o0.z += c0.z; o0.w += c0.w;
            o1.x += c1.x; o1.y += c1.y; o1.z += c1.z; o1.w += c1.w;
        }
        *(float4*)&C[(size_t)r * 128 + tx * 8] = o0;
        *(float4*)&C[(size_t)r * 128 + tx * 8 + 4] = o1;
    }
}

// ---------------- conv1: 1 warp per node, R12 batch-4 body; h1 pre-scaled ------
__global__ void __launch_bounds__(256) k_conv1(const float* __restrict__ b1,
                                               const float* __restrict__ wsc) {
    int c = (blockIdx.x * 256 + threadIdx.x) >> 5;
    int lane = threadIdx.x & 31;
    if (c >= NN) return;
    int s0 = g_off1[c], s1 = g_off1[c + 1];
    float4 acc = make_float4(0.f, 0.f, 0.f, 0.f);
    for (int base = s0; base < s1; base += 32) {
        int m = min(32, s1 - base);
        int sidx = 0;
        if (lane < m) sidx = __ldg(&g_csr1[base + lane]);
        int j = 0;
        for (; j + 4 <= m; j += 4) {
            int i0 = __shfl_sync(0xffffffffu, sidx, j);
            int i1 = __shfl_sync(0xffffffffu, sidx, j + 1);
            int i2 = __shfl_sync(0xffffffffu, sidx, j + 2);
            int i3 = __shfl_sync(0xffffffffu, sidx, j + 3);
            float4 v0 = __ldg((const float4*)&g_h1[(size_t)i0 * DIM + lane * 4]);
            float4 v1 = __ldg((const float4*)&g_h1[(size_t)i1 * DIM + lane * 4]);
            float4 v2 = __ldg((const float4*)&g_h1[(size_t)i2 * DIM + lane * 4]);
            float4 v3 = __ldg((const float4*)&g_h1[(size_t)i3 * DIM + lane * 4]);
            acc.x += (v0.x + v1.x) + (v2.x + v3.x);
            acc.y += (v0.y + v1.y) + (v2.y + v3.y);
            acc.z += (v0.z + v1.z) + (v2.z + v3.z);
            acc.w += (v0.w + v1.w) + (v2.w + v3.w);
        }
        for (; j < m; j++) {
            int s = __shfl_sync(0xffffffffu, sidx, j);
            float4 v = __ldg((const float4*)&g_h1[(size_t)s * DIM + lane * 4]);
            acc.x += v.x; acc.y += v.y; acc.z += v.z; acc.w += v.w;
        }
    }
    float dc = g_dinv[c];
    // h1 already dinv-scaled: self term = dc * h1s[c]
    float4 hc = __ldg((const float4*)&g_h1[(size_t)c * DIM + lane * 4]);
    float4 bb = __ldg((const float4*)&b1[lane * 4]);
    float4 x1;
    x1.x = fmaxf(fmaf(dc, acc.x + hc.x, bb.x), 0.f);
    x1.y = fmaxf(fmaf(dc, acc.y + hc.y, bb.y), 0.f);
    x1.z = fmaxf(fmaf(dc, acc.z + hc.z, bb.z), 0.f);
    x1.w = fmaxf(fmaf(dc, acc.w + hc.w, bb.w), 0.f);
    float4 ws4 = __ldg((const float4*)&wsc[lane * 4]);
    float p = x1.x * ws4.x + x1.y * ws4.y + x1.z * ws4.z + x1.w * ws4.w;
#pragma unroll
    for (int o = 16; o; o >>= 1) p += __shfl_xor_sync(0xffffffffu, p, o);
    if (lane == 0) {
        g_gate[c] = tanhf(p);
        unsigned ub = __float_as_uint(p);
        ub = (ub & 0x80000000u) ? ~ub : (ub | 0x80000000u);
        g_ukey[c] = ub;
        atomicAdd(&g_h16[ub >> 16], 1u);   // fused hist16
    }
    *(float4*)&g_x1[(size_t)c * DIM + lane * 4] = x1;
}

// ---------------- top-K: 2-level 64K-bin histogram select -----------------------
__global__ void k_histlo() {
    int i = blockIdx.x * blockDim.x + threadIdx.x;
    if (i >= NN) return;
    unsigned u = g_ukey[i];
    if ((u >> 16) == g_p16) atomicAdd(&g_hlo[u & 0xFFFFu], 1u);
}

__global__ void __launch_bounds__(1024) k_sel(const unsigned* __restrict__ hist, int phase) {
    __shared__ unsigned tsum[1024];
    __shared__ unsigned vsum[32];
    int t = threadIdx.x;
    unsigned s = 0;
    int base = t * 64;
#pragma unroll 8
    for (int j = 0; j < 64; j++) s += hist[base + j];
    tsum[t] = s;
    __syncthreads();
    if ((t & 31) == 0) {
        unsigned ws = 0;
        for (int j = 0; j < 32; j++) ws += tsum[t + j];
        vsum[t >> 5] = ws;
    }
    __syncthreads();
    if (t == 0) {
        int need = (phase == 0) ? KC : g_need;
        unsigned cum = 0;
        int w;
        for (w = 31; w >= 0; w--) {
            if (cum + vsum[w] >= (unsigned)need) break;
            cum += vsum[w];
        }
        int tt;
        for (tt = w * 32 + 31; tt >= w * 32; tt--) {
            if (cum + tsum[tt] >= (unsigned)need) break;
            cum += tsum[tt];
        }
        for (int d = tt * 64 + 63; d >= tt * 64; d--) {
            unsigned h = hist[d];
            if (cum + h >= (unsigned)need) {
                if (phase == 0) { g_p16 = (unsigned)d; g_need = need - (int)cum; }
                else {
                    g_thr = (g_p16 << 16) | (unsigned)d;
                    g_need = need - (int)cum;
                    g_cnteq = (int)h;
                }
                break;
            }
            cum += h;
        }
    }
}

__global__ void k_keep() {
    int i = blockIdx.x * blockDim.x + threadIdx.x;
    if (i >= NN) return;
    unsigned u = g_ukey[i], T = g_thr;
    g_keep[i] = (u > T) || (u == T && g_cnteq == g_need);
}

// rare path: ordered tie ranking (only runs if cnteq != need)
__global__ void k_ties() {
    if (g_cnteq == g_need) return;
    unsigned T = g_thr;
    int need = g_need;
    __shared__ int wsum[32];
    __shared__ int scarry;
    int tid = threadIdx.x, lane = tid & 31, w = tid >> 5;
    if (tid == 0) scarry = 0;
    __syncthreads();
    for (int base = 0; base < NN; base += 1024) {
        int i = base + tid;
        unsigned u = (i < NN) ? g_ukey[i] : 0u;
        int istie = (i < NN && u == T) ? 1 : 0;
        unsigned m = __ballot_sync(0xffffffffu, istie);
        int excl = __popc(m & ((1u << lane) - 1u));
        if (lane == 0) wsum[w] = __popc(m);
        __syncthreads();
        int wbase = 0;
        for (int ww = 0; ww < w; ww++) wbase += wsum[ww];
        int rank = scarry + wbase + excl;
        if (i < NN)
            g_keep[i] = (u > T) || (istie && rank < need);
        __syncthreads();
        if (tid == 0) {
            int tot = 0;
            for (int ww = 0; ww < 32; ww++) tot += wsum[ww];
            scarry += tot;
        }
        __syncthreads();
    }
}

// ---------------- cluster ids / knode / fallback -------------------------------
__global__ void k_ids() {
    int i = blockIdx.x * blockDim.x + threadIdx.x;
    if (i >= NN) return;
    if (g_keep[i]) {
        g_cid[i] = atomicAdd(&g_kctr, 1);
        int d2 = g_deg2[i];
        atomicMax(&g_maxdeg, d2);
        g_knode[i] = ((unsigned long long)d2 << 38) | (unsigned long long)(unsigned)i;
    } else {
        g_cid[i] = -1;
        g_knode[i] = 0ULL;
    }
}

__global__ void k_fb() {
    int i = blockIdx.x * blockDim.x + threadIdx.x;
    if (i >= NN) return;
    if (g_keep[i] && g_deg2[i] == g_maxdeg) {
        unsigned long long key =
            ((unsigned long long)g_ukey[i] << 17) | (unsigned long long)(0x1FFFFu - (unsigned)i);
        atomicMax(&g_fbkey, key);
    }
}

// NE threads; each handles both directions, using packed knode
__global__ void k_bn(const int* __restrict__ row, const int* __restrict__ col) {
    int e = blockIdx.x * blockDim.x + threadIdx.x;
    if (e >= NE) return;
    int r = row[e], c = col[e];
    unsigned long long kc = __ldg(&g_knode[c]);
    if (kc) {
        unsigned long long key = kc | ((unsigned long long)(0x1FFFFFu - 2u * (unsigned)e) << 17);
        atomicMax(&g_bestkey[r], key);
    }
    unsigned long long kr = __ldg(&g_knode[r]);
    if (kr) {
        unsigned long long key = kr | ((unsigned long long)(0x1FFFFFu - (2u * (unsigned)e + 1u)) << 17);
        atomicMax(&g_bestkey[c], key);
    }
}

// ---------------- fused assign + pool: warp per node ---------------------------
__global__ void __launch_bounds__(256) k_apool() {
    int i = (blockIdx.x * 256 + threadIdx.x) >> 5;
    int lane = threadIdx.x & 31;
    if (i >= NN) return;
    int c;
    if (lane == 0) {
        if (g_keep[i]) {
            c = g_cid[i];
        } else {
            unsigned long long key = g_bestkey[i];
            if (key) {
                c = g_cid[(int)(key & 0x1FFFFULL)];
            } else {
                int fnode = 0x1FFFF - (int)(g_fbkey & 0x1FFFFULL);
                c = g_cid[fnode];
            }
            g_cid[i] = c;
        }
    }
    c = __shfl_sync(0xffffffffu, c, 0);
    float gt = __ldg(&g_gate[i]);
    float4 v = *(const float4*)&g_x1[(size_t)i * DIM + lane * 4];
    v.x *= gt; v.y *= gt; v.z *= gt; v.w *= gt;
    float* dst = &g_sums[(size_t)c * DIM + lane * 4];
    asm volatile("red.global.add.v4.f32 [%0], {%1, %2, %3, %4};"
                 :: "l"(dst), "f"(v.x), "f"(v.y), "f"(v.z), "f"(v.w) : "memory");
    if (lane == 0) atomicAdd(&g_cntf[c], 1.f);
}

// ---------------- coarse graph (conv2) -----------------------------------------
// degc + write packed (cu,cv) per edge into scratch (reuses g_h1 storage)
__global__ void k_degc(const int* __restrict__ row, const int* __restrict__ col,
                       unsigned long long* __restrict__ cucv) {
    int e = blockIdx.x * blockDim.x + threadIdx.x;
    if (e >= NE) return;
    int cu = g_cid[row[e]], cv = g_cid[col[e]];
    cucv[e] = ((unsigned long long)(unsigned)cu << 32) | (unsigned long long)(unsigned)cv;
    if (cu != cv) atomicAdd(&g_degc[cv], 1);
}

__global__ void k_scat2(const unsigned long long* __restrict__ cucv) {
    int e = blockIdx.x * blockDim.x + threadIdx.x;
    if (e >= NE) return;
    unsigned long long p = __ldg(&cucv[e]);
    int cu = (int)(p >> 32), cv = (int)(p & 0xFFFFFFFFULL);
    if (cu != cv) {
        int q = g_off2[cv] + atomicAdd(&g_cur2[cv], 1);
        g_csr2[q] = cu;
    }
}

// conv2: 1 warp per node, R12 batch-4 body
__global__ void __launch_bounds__(256) k_conv2(const float* __restrict__ b2) {
    int c = (blockIdx.x * 256 + threadIdx.x) >> 5;
    int lane = threadIdx.x & 31;
    if (c >= KC) return;
    int s0 = g_off2[c], s1 = g_off2[c + 1];
    float4 acc = make_float4(0.f, 0.f, 0.f, 0.f);
    for (int base = s0; base < s1; base += 32) {
        int m = min(32, s1 - base);
        int sidx = 0;
        if (lane < m) sidx = __ldg(&g_csr2[base + lane]);
        int j = 0;
        for (; j + 4 <= m; j += 4) {
            int i0 = __shfl_sync(0xffffffffu, sidx, j);
            int i1 = __shfl_sync(0xffffffffu, sidx, j + 1);
            int i2 = __shfl_sync(0xffffffffu, sidx, j + 2);
            int i3 = __shfl_sync(0xffffffffu, sidx, j + 3);
            float4 v0 = __ldg((const float4*)&g_h2[(size_t)i0 * DIM + lane * 4]);
            float4 v1 = __ldg((const float4*)&g_h2[(size_t)i1 * DIM + lane * 4]);
            float4 v2 = __ldg((const float4*)&g_h2[(size_t)i2 * DIM + lane * 4]);
            float4 v3 = __ldg((const float4*)&g_h2[(size_t)i3 * DIM + lane * 4]);
            acc.x += (v0.x + v1.x) + (v2.x + v3.x);
            acc.y += (v0.y + v1.y) + (v2.y + v3.y);
            acc.z += (v0.z + v1.z) + (v2.z + v3.z);
            acc.w += (v0.w + v1.w) + (v2.w + v3.w);
        }
        for (; j < m; j++) {
            int s = __shfl_sync(0xffffffffu, sidx, j);
            float4 v = __ldg((const float4*)&g_h2[(size_t)s * DIM + lane * 4]);
            acc.x += v.x; acc.y += v.y; acc.z += v.z; acc.w += v.w;
        }
    }
    float dc = rsqrtf((float)g_degc[c] + 1.f);
    float4 hc = __ldg((const float4*)&g_h2[(size_t)c * DIM + lane * 4]);
    float4 bb = __ldg((const float4*)&b2[lane * 4]);
    float4 o;
    o.x = fmaf(dc, acc.x + hc.x, bb.x);
    o.y = fmaf(dc, acc.y + hc.y, bb.y);
    o.z = fmaf(dc, acc.z + hc.z, bb.z);
    o.w = fmaf(dc, acc.w + hc.w, bb.w);
    *(float4*)&g_xp2[(size_t)c * DIM + lane * 4] = o;
}

// ---------------- tail: zero anything beyond logits -----------------------------
__global__ void k_tail(float* __restrict__ out, int start, int total) {
    int i = start + blockIdx.x * blockDim.x + threadIdx.x;
    if (i < total) out[i] = 0.f;
}

// ================================================================================
extern "C" void kernel_launch(void* const* d_in, const int* in_sizes, int n_in,
                              void* d_out, int out_size) {
    const float* x   = (const float*)d_in[0];
    const int*   ei  = (const int*)d_in[1];
    const int*   row = ei;
    const int*   col = ei + NE;
    const float* W1  = (const float*)d_in[2];
    const float* b1  = (const float*)d_in[3];
    const float* W2  = (const float*)d_in[4];
    const float* b2  = (const float*)d_in[5];
    const float* wsc = (const float*)d_in[6];
    const float* Wsk = (const float*)d_in[7];
    const float* bsk = (const float*)d_in[8];
    float* out = (float*)d_out;

    float *p_h1, *p_x1, *p_sums, *p_cntf, *p_h2, *p_xp2, *p_dinv;
    int *p_degin, *p_off1, *p_degc, *p_off2, *p_bsum, *p_cid;
    unsigned *p_h16, *p_hlo;
    cudaGetSymbolAddress((void**)&p_h1, g_h1);
    cudaGetSymbolAddress((void**)&p_x1, g_x1);
    cudaGetSymbolAddress((void**)&p_sums, g_sums);
    cudaGetSymbolAddress((void**)&p_cntf, g_cntf);
    cudaGetSymbolAddress((void**)&p_h2, g_h2);
    cudaGetSymbolAddress((void**)&p_xp2, g_xp2);
    cudaGetSymbolAddress((void**)&p_dinv, g_dinv);
    cudaGetSymbolAddress((void**)&p_degin, g_degin);
    cudaGetSymbolAddress((void**)&p_off1, g_off1);
    cudaGetSymbolAddress((void**)&p_degc, g_degc);
    cudaGetSymbolAddress((void**)&p_off2, g_off2);
    cudaGetSymbolAddress((void**)&p_bsum, g_bsum);
    cudaGetSymbolAddress((void**)&p_cid, g_cid);
    cudaGetSymbolAddress((void**)&p_h16, g_h16);
    cudaGetSymbolAddress((void**)&p_hlo, g_hlo);
    unsigned long long* p_cucv = (unsigned long long*)p_h1;  // reuse dead h1 scratch

    const int TB = 256;
    const int NB1 = (NN + 1023) / 1024;   // 49
    const int NB2 = (KC + 1023) / 1024;   // 5

    k_zero<<<(KC * DIM + TB - 1) / TB, TB>>>();
    k_deg<<<(NE + TB - 1) / TB, TB>>>(row, col);

    // h1 = rsqrt(degin+1) ⊙ (x @ W1)  (pre-scaled for conv1)
    k_gemm<<<(NN + 127) / 128, 256>>>(x, W1, p_h1, NN, p_degin, nullptr,
                                      nullptr, nullptr, nullptr);

    // CSR by col (multi-block scan; dinv fused into pass 1)
    k_scanp<<<NB1, 1024>>>(p_degin, p_off1, p_bsum, NN, p_dinv);
    k_scanb<<<1, 32>>>(p_bsum, NB1, p_off1, NN);
    k_scana<<<NB1, 1024>>>(p_off1, p_bsum, NN);
    k_scat1<<<(NE + TB - 1) / TB, TB>>>(row, col);

    // conv1 + relu + score + gate (+ fused hist16), 1 warp/node
    k_conv1<<<(NN * 32 + TB - 1) / TB, TB>>>(b1, wsc);

    // top-K (2-level 64K-bin histogram; hist16 filled in conv1)
    k_sel<<<1, 1024>>>(p_h16, 0);
    k_histlo<<<(NN + TB - 1) / TB, TB>>>();
    k_sel<<<1, 1024>>>(p_hlo, 1);
    k_keep<<<(NN + TB - 1) / TB, TB>>>();
    k_ties<<<1, 1024>>>();

    k_ids<<<(NN + TB - 1) / TB, TB>>>();
    k_fb<<<(NN + TB - 1) / TB, TB>>>();
    k_bn<<<(NE + TB - 1) / TB, TB>>>(row, col);

    // fused assign + pool (warp per node, vector red); h1 dead after conv1
    k_apool<<<(NN * 32 + TB - 1) / TB, TB>>>();

    // coarse graph degrees + packed edge cache + CSR
    k_degc<<<(NE + TB - 1) / TB, TB>>>(row, col, p_cucv);
    k_scanp<<<NB2, 1024>>>(p_degc, p_off2, p_bsum, KC, nullptr);
    k_scanb<<<1, 32>>>(p_bsum, NB2, p_off2, KC);
    k_scana<<<NB2, 1024>>>(p_off2, p_bsum, KC);
    k_scat2<<<(NE + TB - 1) / TB, TB>>>(p_cucv);

    // h2 = (rsqrt(degc+1)/cnt) ⊙ (sums @ W2) ; conv2 (1 warp/node)
    k_gemm<<<(KC + 127) / 128, 256>>>(p_sums, W2, p_h2, KC, p_degc, p_cntf,
                                      nullptr, nullptr, nullptr);
    k_conv2<<<(KC * 32 + TB - 1) / TB, TB>>>(b2);

    // logits = x1 @ W_skip + b_skip + x_p2[cid]
    k_gemm<<<(NN + 127) / 128, 256>>>(p_x1, Wsk, out, NN, nullptr, nullptr,
                                      bsk, p_xp2, p_cid);

    int tail = out_size - NN * DIM;
    if (tail > 0)
        k_tail<<<(tail + TB - 1) / TB, TB>>>(out, NN * DIM, out_size);
}

// round 17
// speedup vs baseline: 2.5967x; 2.5967x over previous
#include <cuda_runtime.h>
#include <cstdint>

#define NN 50000
#define NE 800000
#define DIM 128
#define KC 5000

// ---------------- scratch (static device globals; no allocation) -------------
__device__ float g_h1[NN * DIM];     // dinv ⊙ (x@W1); reused as edge scratch after conv1
__device__ float g_x1[NN * DIM];
__device__ float g_gate[NN];
__device__ float g_dinv[NN];
__device__ unsigned g_ukey[NN];
__device__ int g_keep[NN];
__device__ int g_cid[NN];
__device__ int g_degin[NN];
__device__ int g_deg2[NN];
__device__ int g_off1[NN + 1];
__device__ int g_cur1[NN];
__device__ int g_csr1[NE];
__device__ unsigned long long g_bestkey[NN];
__device__ unsigned long long g_knode[NN];
__device__ float g_sums[KC * DIM];
__device__ float g_cntf[KC];
__device__ float g_h2[KC * DIM];     // (dinvc/cnt) ⊙ (sums@W2)
__device__ float g_xp2[KC * DIM];
__device__ int g_degc[KC];
__device__ int g_off2[KC + 1];
__device__ int g_cur2[KC];
__device__ int g_csr2[NE];
__device__ int g_bsum[64];
__device__ unsigned g_h16[65536];
__device__ unsigned g_hlo[65536];
__device__ unsigned g_p16;
__device__ unsigned g_thr;
__device__ int g_need;
__device__ int g_cnteq;
__device__ unsigned long long g_fbkey;
__device__ int g_kctr;
__device__ int g_maxdeg;

// ---------------- init / zero ------------------------------------------------
__global__ void k_zero() {
    int i = blockIdx.x * blockDim.x + threadIdx.x;
    if (i < NN) { g_degin[i] = 0; g_deg2[i] = 0; g_cur1[i] = 0; g_bestkey[i] = 0ULL; }
    if (i < KC) { g_cntf[i] = 0.f; g_degc[i] = 0; g_cur2[i] = 0; }
    if (i < KC * DIM) g_sums[i] = 0.f;
    if (i < 65536) { g_h16[i] = 0u; g_hlo[i] = 0u; }
    if (i == 0) { g_fbkey = 0ULL; g_kctr = 0; g_maxdeg = 0; }
}

// ---------------- degrees ----------------------------------------------------
__global__ void k_deg(const int* __restrict__ row, const int* __restrict__ col) {
    int e = blockIdx.x * blockDim.x + threadIdx.x;
    if (e >= NE) return;
    atomicAdd(&g_degin[col[e]], 1);
    atomicAdd(&g_deg2[row[e]], 1);
}

// ---------------- multi-block 3-phase exclusive scan (+optional dinv) ----------
__global__ void k_scanp(const int* __restrict__ in, int* __restrict__ out,
                        int* __restrict__ bsum, int n, float* __restrict__ dinv) {
    __shared__ int wsum[32];
    int tid = threadIdx.x, lane = tid & 31, w = tid >> 5;
    int gid = blockIdx.x * 1024 + tid;
    int v = (gid < n) ? in[gid] : 0;
    if (dinv && gid < n) dinv[gid] = rsqrtf((float)v + 1.f);
    int sc = v;
#pragma unroll
    for (int o = 1; o < 32; o <<= 1) {
        int t2 = __shfl_up_sync(0xffffffffu, sc, o);
        if (lane >= o) sc += t2;
    }
    if (lane == 31) wsum[w] = sc;
    __syncthreads();
    if (w == 0) {
        int ws = wsum[lane];
#pragma unroll
        for (int o = 1; o < 32; o <<= 1) {
            int t2 = __shfl_up_sync(0xffffffffu, ws, o);
            if (lane >= o) ws += t2;
        }
        wsum[lane] = ws;
    }
    __syncthreads();
    int excl = (w ? wsum[w - 1] : 0) + sc - v;
    if (gid < n) out[gid] = excl;
    if (tid == 0) bsum[blockIdx.x] = wsum[31];
}

// single-warp scan of up to 64 block sums (verified R16)
__global__ void k_scanb(int* __restrict__ bsum, int nb, int* __restrict__ out, int n) {
    int lane = threadIdx.x;   // 32 threads
    int v0 = (lane < nb) ? bsum[lane] : 0;
    int v1 = (lane + 32 < nb) ? bsum[lane + 32] : 0;
    int s0 = v0;
#pragma unroll
    for (int o = 1; o < 32; o <<= 1) {
        int t = __shfl_up_sync(0xffffffffu, s0, o);
        if (lane >= o) s0 += t;
    }
    int tot0 = __shfl_sync(0xffffffffu, s0, 31);
    int s1 = v1;
#pragma unroll
    for (int o = 1; o < 32; o <<= 1) {
        int t = __shfl_up_sync(0xffffffffu, s1, o);
        if (lane >= o) s1 += t;
    }
    s1 += tot0;
    if (lane < nb) bsum[lane] = s0 - v0;
    if (lane + 32 < nb) bsum[lane + 32] = s1 - v1;
    if (lane == 31) out[n] = s1;
}

__global__ void k_scana(int* __restrict__ out, const int* __restrict__ bsum, int n) {
    int gid = blockIdx.x * 1024 + threadIdx.x;
    if (gid < n) out[gid] += bsum[blockIdx.x];
}

// ---------------- CSR scatter (group edges by col) ----------------------------
__global__ void k_scat1(const int* __restrict__ row, const int* __restrict__ col) {
    int e = blockIdx.x * blockDim.x + threadIdx.x;
    if (e >= NE) return;
    int c = col[e];
    int p = g_off1[c] + atomicAdd(&g_cur1[c], 1);
    g_csr1[p] = row[e];
}

// ---------------- fp32 SMEM GEMM: 128x128 tile, 8x8 per-thread ----------------
__global__ void __launch_bounds__(256) k_gemm(
    const float* __restrict__ A, const float* __restrict__ W,
    float* __restrict__ C, int M,
    const int* __restrict__ degA,
    const float* __restrict__ cntA,
    const float* __restrict__ bias,
    const float* __restrict__ bcast, const int* __restrict__ cid)
{
    __shared__ float As[16][132];   // transposed: As[k][row], 128 rows
    __shared__ float Ws[16][128];
    int tid = threadIdx.x;
    int tx = tid & 15, ty = tid >> 4;       // 16 x 16 thread map
    int row0 = blockIdx.x * 128;
    float acc[8][8];
#pragma unroll
    for (int i = 0; i < 8; i++)
#pragma unroll
        for (int j = 0; j < 8; j++) acc[i][j] = 0.f;

    for (int kt = 0; kt < 128; kt += 16) {
#pragma unroll
        for (int it = 0; it < 2; it++) {     // A: 128 rows x 16 k -> 512 float4
            int idx = tid + it * 256;        // 0..511
            int r = idx >> 2;                // 0..127
            int k4 = (idx & 3) * 4;
            int gr = row0 + r;
            float4 a = (gr < M) ? *(const float4*)&A[(size_t)gr * 128 + kt + k4]
                                : make_float4(0.f, 0.f, 0.f, 0.f);
            As[k4 + 0][r] = a.x; As[k4 + 1][r] = a.y;
            As[k4 + 2][r] = a.z; As[k4 + 3][r] = a.w;
        }
#pragma unroll
        for (int it = 0; it < 2; it++) {     // W: 16 k x 128 n
            int idx = tid + it * 256;
            int kk = idx >> 5, n4 = idx & 31;
            *(float4*)&Ws[kk][n4 * 4] = *(const float4*)&W[(size_t)(kt + kk) * 128 + n4 * 4];
        }
        __syncthreads();
#pragma unroll
        for (int kk = 0; kk < 16; kk++) {
            float4 a0 = *(const float4*)&As[kk][ty * 8];
            float4 a1 = *(const float4*)&As[kk][ty * 8 + 4];
            float4 w0 = *(const float4*)&Ws[kk][tx * 8];
            float4 w1 = *(const float4*)&Ws[kk][tx * 8 + 4];
            float a_[8] = {a0.x, a0.y, a0.z, a0.w, a1.x, a1.y, a1.z, a1.w};
            float w_[8] = {w0.x, w0.y, w0.z, w0.w, w1.x, w1.y, w1.z, w1.w};
#pragma unroll
            for (int i = 0; i < 8; i++)
#pragma unroll
                for (int j = 0; j < 8; j++) acc[i][j] += a_[i] * w_[j];
        }
        __syncthreads();
    }
#pragma unroll
    for (int i = 0; i < 8; i++) {
        int r = row0 + ty * 8 + i;
        if (r >= M) continue;
        float rs = 1.f;
        if (degA) rs = rsqrtf((float)degA[r] + 1.f);
        if (cntA) rs /= fmaxf(cntA[r], 1.f);
        float4 o0 = make_float4(acc[i][0], acc[i][1], acc[i][2], acc[i][3]);
        float4 o1 = make_float4(acc[i][4], acc[i][5], acc[i][6], acc[i][7]);
        o0.x *= rs; o0.y *= rs; o0.z *= rs; o0.w *= rs;
        o1.x *= rs; o1.y *= rs; o1.z *= rs; o1.w *= rs;
        if (bias) {
            float4 b0 = *(const float4*)&bias[tx * 8];
            float4 b1v = *(const float4*)&bias[tx * 8 + 4];
            o0.x += b0.x; o0.y += b0.y; o0.z += b0.z; o0.w += b0.w;
            o1.x += b1v.x; o1.y += b1v.y; o1.z += b1v.z; o1.w += b1v.w;
        }
        if (bcast) {
            const float* bc = &bcast[(size_t)cid[r] * 128];
            float4 c0 = *(const float4*)&bc[tx * 8];
            float4 c1 = *(const float4*)&bc[tx * 8 + 4];
            o0.x += c0.x; o0.y += c0.y; o0.z += c0.z; o0.w += c0.w;
            o1.x += c1.x; o1.y += c1.y; o1.z += c1.z; o1.w += c1.w;
        }
        *(float4*)&C[(size_t)r * 128 + tx * 8] = o0;
        *(float4*)&C[(size_t)r * 128 + tx * 8 + 4] = o1;
    }
}

// ---------------- conv1: 4 warps/node (block-per-node), h1 pre-scaled ----------
__global__ void __launch_bounds__(128) k_conv1(const float* __restrict__ b1,
                                               const float* __restrict__ wsc) {
    int c = blockIdx.x;
    int lane = threadIdx.x & 31, w = threadIdx.x >> 5;
    int s0 = g_off1[c], s1 = g_off1[c + 1];
    int deg = s1 - s0;
    int chunk = (deg + 3) >> 2;                 // edges per warp
    int cs = s0 + w * chunk;
    int ce = min(cs + chunk, s1);
    float4 acc = make_float4(0.f, 0.f, 0.f, 0.f);
    for (int base = cs; base < ce; base += 32) {
        int m = min(32, ce - base);
        int sidx = 0;
        if (lane < m) sidx = __ldg(&g_csr1[base + lane]);
        int j = 0;
        for (; j + 4 <= m; j += 4) {
            int i0 = __shfl_sync(0xffffffffu, sidx, j);
            int i1 = __shfl_sync(0xffffffffu, sidx, j + 1);
            int i2 = __shfl_sync(0xffffffffu, sidx, j + 2);
            int i3 = __shfl_sync(0xffffffffu, sidx, j + 3);
            float4 v0 = __ldg((const float4*)&g_h1[(size_t)i0 * DIM + lane * 4]);
            float4 v1 = __ldg((const float4*)&g_h1[(size_t)i1 * DIM + lane * 4]);
            float4 v2 = __ldg((const float4*)&g_h1[(size_t)i2 * DIM + lane * 4]);
            float4 v3 = __ldg((const float4*)&g_h1[(size_t)i3 * DIM + lane * 4]);
            acc.x += (v0.x + v1.x) + (v2.x + v3.x);
            acc.y += (v0.y + v1.y) + (v2.y + v3.y);
            acc.z += (v0.z + v1.z) + (v2.z + v3.z);
            acc.w += (v0.w + v1.w) + (v2.w + v3.w);
        }
        for (; j < m; j++) {
            int s = __shfl_sync(0xffffffffu, sidx, j);
            float4 v = __ldg((const float4*)&g_h1[(size_t)s * DIM + lane * 4]);
            acc.x += v.x; acc.y += v.y; acc.z += v.z; acc.w += v.w;
        }
    }
    __shared__ float4 part[4][32];
    part[w][lane] = acc;
    __syncthreads();
    if (w == 0) {
        float4 a0 = part[0][lane], a1 = part[1][lane];
        float4 a2 = part[2][lane], a3 = part[3][lane];
        float4 tot = make_float4((a0.x + a1.x) + (a2.x + a3.x),
                                 (a0.y + a1.y) + (a2.y + a3.y),
                                 (a0.z + a1.z) + (a2.z + a3.z),
                                 (a0.w + a1.w) + (a2.w + a3.w));
        float dc = g_dinv[c];
        // h1 already dinv-scaled: self term = dc * h1s[c]
        float4 hc = __ldg((const float4*)&g_h1[(size_t)c * DIM + lane * 4]);
        float4 bb = __ldg((const float4*)&b1[lane * 4]);
        float4 x1;
        x1.x = fmaxf(fmaf(dc, tot.x + hc.x, bb.x), 0.f);
        x1.y = fmaxf(fmaf(dc, tot.y + hc.y, bb.y), 0.f);
        x1.z = fmaxf(fmaf(dc, tot.z + hc.z, bb.z), 0.f);
        x1.w = fmaxf(fmaf(dc, tot.w + hc.w, bb.w), 0.f);
        float4 ws4 = __ldg((const float4*)&wsc[lane * 4]);
        float p = x1.x * ws4.x + x1.y * ws4.y + x1.z * ws4.z + x1.w * ws4.w;
#pragma unroll
        for (int o = 16; o; o >>= 1) p += __shfl_xor_sync(0xffffffffu, p, o);
        if (lane == 0) {
            g_gate[c] = tanhf(p);
            unsigned ub = __float_as_uint(p);
            ub = (ub & 0x80000000u) ? ~ub : (ub | 0x80000000u);
            g_ukey[c] = ub;
            atomicAdd(&g_h16[ub >> 16], 1u);   // fused hist16
        }
        *(float4*)&g_x1[(size_t)c * DIM + lane * 4] = x1;
    }
}

// ---------------- top-K: 2-level 64K-bin histogram select -----------------------
__global__ void k_histlo() {
    int i = blockIdx.x * blockDim.x + threadIdx.x;
    if (i >= NN) return;
    unsigned u = g_ukey[i];
    if ((u >> 16) == g_p16) atomicAdd(&g_hlo[u & 0xFFFFu], 1u);
}

__global__ void __launch_bounds__(1024) k_sel(const unsigned* __restrict__ hist, int phase) {
    __shared__ unsigned tsum[1024];
    __shared__ unsigned vsum[32];
    int t = threadIdx.x;
    unsigned s = 0;
    int base = t * 64;
#pragma unroll 8
    for (int j = 0; j < 64; j++) s += hist[base + j];
    tsum[t] = s;
    __syncthreads();
    if ((t & 31) == 0) {
        unsigned ws = 0;
        for (int j = 0; j < 32; j++) ws += tsum[t + j];
        vsum[t >> 5] = ws;
    }
    __syncthreads();
    if (t == 0) {
        int need = (phase == 0) ? KC : g_need;
        unsigned cum = 0;
        int w;
        for (w = 31; w >= 0; w--) {
            if (cum + vsum[w] >= (unsigned)need) break;
            cum += vsum[w];
        }
        int tt;
        for (tt = w * 32 + 31; tt >= w * 32; tt--) {
            if (cum + tsum[tt] >= (unsigned)need) break;
            cum += tsum[tt];
        }
        for (int d = tt * 64 + 63; d >= tt * 64; d--) {
            unsigned h = hist[d];
            if (cum + h >= (unsigned)need) {
                if (phase == 0) { g_p16 = (unsigned)d; g_need = need - (int)cum; }
                else {
                    g_thr = (g_p16 << 16) | (unsigned)d;
                    g_need = need - (int)cum;
                    g_cnteq = (int)h;
                }
                break;
            }
            cum += h;
        }
    }
}

__global__ void k_keep() {
    int i = blockIdx.x * blockDim.x + threadIdx.x;
    if (i >= NN) return;
    unsigned u = g_ukey[i], T = g_thr;
    g_keep[i] = (u > T) || (u == T && g_cnteq == g_need);
}

// rare path: ordered tie ranking (only runs if cnteq != need)
__global__ void k_ties() {
    if (g_cnteq == g_need) return;
    unsigned T = g_thr;
    int need = g_need;
    __shared__ int wsum[32];
    __shared__ int scarry;
    int tid = threadIdx.x, lane = tid & 31, w = tid >> 5;
    if (tid == 0) scarry = 0;
    __syncthreads();
    for (int base = 0; base < NN; base += 1024) {
        int i = base + tid;
        unsigned u = (i < NN) ? g_ukey[i] : 0u;
        int istie = (i < NN && u == T) ? 1 : 0;
        unsigned m = __ballot_sync(0xffffffffu, istie);
        int excl = __popc(m & ((1u << lane) - 1u));
        if (lane == 0) wsum[w] = __popc(m);
        __syncthreads();
        int wbase = 0;
        for (int ww = 0; ww < w; ww++) wbase += wsum[ww];
        int rank = scarry + wbase + excl;
        if (i < NN)
            g_keep[i] = (u > T) || (istie && rank < need);
        __syncthreads();
        if (tid == 0) {
            int tot = 0;
            for (int ww = 0; ww < 32; ww++) tot += wsum[ww];
            scarry += tot;
        }
        __syncthreads();
    }
}

// ---------------- cluster ids / knode / fallback -------------------------------
__global__ void k_ids() {
    int i = blockIdx.x * blockDim.x + threadIdx.x;
    if (i >= NN) return;
    if (g_keep[i]) {
        g_cid[i] = atomicAdd(&g_kctr, 1);
        int d2 = g_deg2[i];
        atomicMax(&g_maxdeg, d2);
        g_knode[i] = ((unsigned long long)d2 << 38) | (unsigned long long)(unsigned)i;
    } else {
        g_cid[i] = -1;
        g_knode[i] = 0ULL;
    }
}

__global__ void k_fb() {
    int i = blockIdx.x * blockDim.x + threadIdx.x;
    if (i >= NN) return;
    if (g_keep[i] && g_deg2[i] == g_maxdeg) {
        unsigned long long key =
            ((unsigned long long)g_ukey[i] << 17) | (unsigned long long)(0x1FFFFu - (unsigned)i);
        atomicMax(&g_fbkey, key);
    }
}

// NE threads; each handles both directions, using packed knode
__global__ void k_bn(const int* __restrict__ row, const int* __restrict__ col) {
    int e = blockIdx.x * blockDim.x + threadIdx.x;
    if (e >= NE) return;
    int r = row[e], c = col[e];
    unsigned long long kc = __ldg(&g_knode[c]);
    if (kc) {
        unsigned long long key = kc | ((unsigned long long)(0x1FFFFFu - 2u * (unsigned)e) << 17);
        atomicMax(&g_bestkey[r], key);
    }
    unsigned long long kr = __ldg(&g_knode[r]);
    if (kr) {
        unsigned long long key = kr | ((unsigned long long)(0x1FFFFFu - (2u * (unsigned)e + 1u)) << 17);
        atomicMax(&g_bestkey[c], key);
    }
}

// ---------------- fused assign + pool: warp per node ---------------------------
__global__ void __launch_bounds__(256) k_apool() {
    int i = (blockIdx.x * 256 + threadIdx.x) >> 5;
    int lane = threadIdx.x & 31;
    if (i >= NN) return;
    int c;
    if (lane == 0) {
        if (g_keep[i]) {
            c = g_cid[i];
        } else {
            unsigned long long key = g_bestkey[i];
            if (key) {
                c = g_cid[(int)(key & 0x1FFFFULL)];
            } else {
                int fnode = 0x1FFFF - (int)(g_fbkey & 0x1FFFFULL);
                c = g_cid[fnode];
            }
            g_cid[i] = c;
        }
    }
    c = __shfl_sync(0xffffffffu, c, 0);
    float gt = __ldg(&g_gate[i]);
    float4 v = *(const float4*)&g_x1[(size_t)i * DIM + lane * 4];
    v.x *= gt; v.y *= gt; v.z *= gt; v.w *= gt;
    float* dst = &g_sums[(size_t)c * DIM + lane * 4];
    asm volatile("red.global.add.v4.f32 [%0], {%1, %2, %3, %4};"
                 :: "l"(dst), "f"(v.x), "f"(v.y), "f"(v.z), "f"(v.w) : "memory");
    if (lane == 0) atomicAdd(&g_cntf[c], 1.f);
}

// ---------------- coarse graph (conv2) -----------------------------------------
// degc + write packed (cu,cv) per edge into scratch (reuses g_h1 storage)
__global__ void k_degc(const int* __restrict__ row, const int* __restrict__ col,
                       unsigned long long* __restrict__ cucv) {
    int e = blockIdx.x * blockDim.x + threadIdx.x;
    if (e >= NE) return;
    int cu = g_cid[row[e]], cv = g_cid[col[e]];
    cucv[e] = ((unsigned long long)(unsigned)cu << 32) | (unsigned long long)(unsigned)cv;
    if (cu != cv) atomicAdd(&g_degc[cv], 1);
}

__global__ void k_scat2(const unsigned long long* __restrict__ cucv) {
    int e = blockIdx.x * blockDim.x + threadIdx.x;
    if (e >= NE) return;
    unsigned long long p = __ldg(&cucv[e]);
    int cu = (int)(p >> 32), cv = (int)(p & 0xFFFFFFFFULL);
    if (cu != cv) {
        int q = g_off2[cv] + atomicAdd(&g_cur2[cv], 1);
        g_csr2[q] = cu;
    }
}

// conv2: 4 warps/node (block-per-node), shfl-batched indices
__global__ void __launch_bounds__(128) k_conv2(const float* __restrict__ b2) {
    int c = blockIdx.x;
    int lane = threadIdx.x & 31, w = threadIdx.x >> 5;
    int s0 = g_off2[c], s1 = g_off2[c + 1];
    int deg = s1 - s0;
    int chunk = (deg + 3) >> 2;
    int cs = s0 + w * chunk;
    int ce = min(cs + chunk, s1);
    float4 acc = make_float4(0.f, 0.f, 0.f, 0.f);
    for (int base = cs; base < ce; base += 32) {
        int m = min(32, ce - base);
        int sidx = 0;
        if (lane < m) sidx = __ldg(&g_csr2[base + lane]);
        int j = 0;
        for (; j + 4 <= m; j += 4) {
            int i0 = __shfl_sync(0xffffffffu, sidx, j);
            int i1 = __shfl_sync(0xffffffffu, sidx, j + 1);
            int i2 = __shfl_sync(0xffffffffu, sidx, j + 2);
            int i3 = __shfl_sync(0xffffffffu, sidx, j + 3);
            float4 v0 = __ldg((const float4*)&g_h2[(size_t)i0 * DIM + lane * 4]);
            float4 v1 = __ldg((const float4*)&g_h2[(size_t)i1 * DIM + lane * 4]);
            float4 v2 = __ldg((const float4*)&g_h2[(size_t)i2 * DIM + lane * 4]);
            float4 v3 = __ldg((const float4*)&g_h2[(size_t)i3 * DIM + lane * 4]);
            acc.x += (v0.x + v1.x) + (v2.x + v3.x);
            acc.y += (v0.y + v1.y) + (v2.y + v3.y);
            acc.z += (v0.z + v1.z) + (v2.z + v3.z);
            acc.w += (v0.w + v1.w) + (v2.w + v3.w);
        }
        for (; j < m; j++) {
            int s = __shfl_sync(0xffffffffu, sidx, j);
            float4 v = __ldg((const float4*)&g_h2[(size_t)s * DIM + lane * 4]);
            acc.x += v.x; acc.y += v.y; acc.z += v.z; acc.w += v.w;
        }
    }
    __shared__ float4 part[4][32];
    part[w][lane] = acc;
    __syncthreads();
    if (w == 0) {
        float4 a0 = part[0][lane], a1 = part[1][lane];
        float4 a2 = part[2][lane], a3 = part[3][lane];
        float dc = rsqrtf((float)g_degc[c] + 1.f);
        float4 hc = __ldg((const float4*)&g_h2[(size_t)c * DIM + lane * 4]);
        float4 bb = __ldg((const float4*)&b2[lane * 4]);
        float4 o;
        o.x = fmaf(dc, (a0.x + a1.x) + (a2.x + a3.x) + hc.x, bb.x);
        o.y = fmaf(dc, (a0.y + a1.y) + (a2.y + a3.y) + hc.y, bb.y);
        o.z = fmaf(dc, (a0.z + a1.z) + (a2.z + a3.z) + hc.z, bb.z);
        o.w = fmaf(dc, (a0.w + a1.w) + (a2.w + a3.w) + hc.w, bb.w);
        *(float4*)&g_xp2[(size_t)c * DIM + lane * 4] = o;
    }
}

// ---------------- tail: zero anything beyond logits -----------------------------
__global__ void k_tail(float* __restrict__ out, int start, int total) {
    int i = start + blockIdx.x * blockDim.x + threadIdx.x;
    if (i < total) out[i] = 0.f;
}

// ================================================================================
extern "C" void kernel_launch(void* const* d_in, const int* in_sizes, int n_in,
                              void* d_out, int out_size) {
    const float* x   = (const float*)d_in[0];
    const int*   ei  = (const int*)d_in[1];
    const int*   row = ei;
    const int*   col = ei + NE;
    const float* W1  = (const float*)d_in[2];
    const float* b1  = (const float*)d_in[3];
    const float* W2  = (const float*)d_in[4];
    const float* b2  = (const float*)d_in[5];
    const float* wsc = (const float*)d_in[6];
    const float* Wsk = (const float*)d_in[7];
    const float* bsk = (const float*)d_in[8];
    float* out = (float*)d_out;

    float *p_h1, *p_x1, *p_sums, *p_cntf, *p_h2, *p_xp2, *p_dinv;
    int *p_degin, *p_off1, *p_degc, *p_off2, *p_bsum, *p_cid;
    unsigned *p_h16, *p_hlo;
    cudaGetSymbolAddress((void**)&p_h1, g_h1);
    cudaGetSymbolAddress((void**)&p_x1, g_x1);
    cudaGetSymbolAddress((void**)&p_sums, g_sums);
    cudaGetSymbolAddress((void**)&p_cntf, g_cntf);
    cudaGetSymbolAddress((void**)&p_h2, g_h2);
    cudaGetSymbolAddress((void**)&p_xp2, g_xp2);
    cudaGetSymbolAddress((void**)&p_dinv, g_dinv);
    cudaGetSymbolAddress((void**)&p_degin, g_degin);
    cudaGetSymbolAddress((void**)&p_off1, g_off1);
    cudaGetSymbolAddress((void**)&p_degc, g_degc);
    cudaGetSymbolAddress((void**)&p_off2, g_off2);
    cudaGetSymbolAddress((void**)&p_bsum, g_bsum);
    cudaGetSymbolAddress((void**)&p_cid, g_cid);
    cudaGetSymbolAddress((void**)&p_h16, g_h16);
    cudaGetSymbolAddress((void**)&p_hlo, g_hlo);
    unsigned long long* p_cucv = (unsigned long long*)p_h1;  // reuse dead h1 scratch

    const int TB = 256;
    const int NB1 = (NN + 1023) / 1024;   // 49
    const int NB2 = (KC + 1023) / 1024;   // 5

    k_zero<<<(KC * DIM + TB - 1) / TB, TB>>>();
    k_deg<<<(NE + TB - 1) / TB, TB>>>(row, col);

    // h1 = rsqrt(degin+1) ⊙ (x @ W1)  (pre-scaled for conv1)
    k_gemm<<<(NN + 127) / 128, 256>>>(x, W1, p_h1, NN, p_degin, nullptr,
                                      nullptr, nullptr, nullptr);

    // CSR by col (multi-block scan; dinv fused into pass 1)
    k_scanp<<<NB1, 1024>>>(p_degin, p_off1, p_bsum, NN, p_dinv);
    k_scanb<<<1, 32>>>(p_bsum, NB1, p_off1, NN);
    k_scana<<<NB1, 1024>>>(p_off1, p_bsum, NN);
    k_scat1<<<(NE + TB - 1) / TB, TB>>>(row, col);

    // conv1 + relu + score + gate (+ fused hist16), 4 warps/node
    k_conv1<<<NN, 128>>>(b1, wsc);

    // top-K (2-level 64K-bin histogram; hist16 filled in conv1)
    k_sel<<<1, 1024>>>(p_h16, 0);
    k_histlo<<<(NN + TB - 1) / TB, TB>>>();
    k_sel<<<1, 1024>>>(p_hlo, 1);
    k_keep<<<(NN + TB - 1) / TB, TB>>>();
    k_ties<<<1, 1024>>>();

    k_ids<<<(NN + TB - 1) / TB, TB>>>();
    k_fb<<<(NN + TB - 1) / TB, TB>>>();
    k_bn<<<(NE + TB - 1) / TB, TB>>>(row, col);

    // fused assign + pool (warp per node, vector red); h1 dead after conv1
    k_apool<<<(NN * 32 + TB - 1) / TB, TB>>>();

    // coarse graph degrees + packed edge cache + CSR
    k_degc<<<(NE + TB - 1) / TB, TB>>>(row, col, p_cucv);
    k_scanp<<<NB2, 1024>>>(p_degc, p_off2, p_bsum, KC, nullptr);
    k_scanb<<<1, 32>>>(p_bsum, NB2, p_off2, KC);
    k_scana<<<NB2, 1024>>>(p_off2, p_bsum, KC);
    k_scat2<<<(NE + TB - 1) / TB, TB>>>(p_cucv);

    // h2 = (rsqrt(degc+1)/cnt) ⊙ (sums @ W2) ; conv2 (4 warps/node)
    k_gemm<<<(KC + 127) / 128, 256>>>(p_sums, W2, p_h2, KC, p_degc, p_cntf,
                                      nullptr, nullptr, nullptr);
    k_conv2<<<KC, 128>>>(b2);

    // logits = x1 @ W_skip + b_skip + x_p2[cid]
    k_gemm<<<(NN + 127) / 128, 256>>>(p_x1, Wsk, out, NN, nullptr, nullptr,
                                      bsk, p_xp2, p_cid);

    int tail = out_size - NN * DIM;
    if (tail > 0)
        k_tail<<<(tail + TB - 1) / TB, TB>>>(out, NN * DIM, out_size);
}